// round 1
// baseline (speedup 1.0000x reference)
#include <cuda_runtime.h>

#define Bz   4
#define Cc   64
#define Hh   64
#define Ww   64
#define HW   (Hh*Ww)
#define CHW  (Cc*HW)
#define PATCH 9
#define HALF  4
#define TY    2

#define SROW   72            // 4 halo + 64 + 4 halo
#define SROWS  (TY + 2*HALF) // 10
#define SMEM_FLOATS (Cc*SROWS*SROW)      // 46080
#define SMEM_BYTES  (SMEM_FLOATS*4)      // 184320
#define NTHREADS 288

// scratch: inverse L2 norms per pixel, [feat][b][y*W+x]
__device__ float g_inv[2][Bz][HW];

// ---------------------------------------------------------------------------
// Kernel 1: per-pixel inverse norms for both features
// ---------------------------------------------------------------------------
__global__ void invnorm_kernel(const float* __restrict__ f1,
                               const float* __restrict__ f2) {
    int idx  = blockIdx.x * blockDim.x + threadIdx.x;   // 0..32767
    int feat = idx >> 14;
    int pix  = idx & 16383;          // b*4096 + y*64 + x
    int b    = pix >> 12;
    int yx   = pix & 4095;
    const float* src = (feat ? f2 : f1) + b * CHW + yx;
    float s = 0.f;
#pragma unroll
    for (int c = 0; c < Cc; ++c) {
        float v = src[c * HW];
        s += v * v;
    }
    g_inv[feat][b][yx] = rsqrtf(s + 1e-6f);
}

// ---------------------------------------------------------------------------
// Kernel 2: fused normalized correlation + relu
//   grid = B * (H/TY) = 128 blocks, 288 threads (warp = dy, lane = (ty, xg))
// ---------------------------------------------------------------------------
__global__ __launch_bounds__(NTHREADS, 1)
void corr_kernel(const float* __restrict__ f1,
                 const float* __restrict__ f2,
                 float* __restrict__ out) {
    extern __shared__ float s_f2[];   // [c][SROWS][SROW], normalized f2 tile

    const int b  = blockIdx.x >> 5;        // /32
    const int y0 = (blockIdx.x & 31) * TY;
    const int tid = threadIdx.x;

    // ---- stage normalized f2 tile (rows y0-4 .. y0+5, x halo = always OOB = 0)
    const float* inv2 = &g_inv[1][b][0];
    const float* f2b  = f2 + b * CHW;
    for (int i = tid; i < Cc * SROWS * 16; i += NTHREADS) {
        int c   = i / 160;
        int rem = i - c * 160;
        int r   = rem >> 4;
        int x   = (rem & 15) << 2;
        int yy  = y0 + r - HALF;
        float4 val = make_float4(0.f, 0.f, 0.f, 0.f);
        if (yy >= 0 && yy < Hh) {
            float4 v  = *(const float4*)(f2b  + c * HW + yy * Ww + x);
            float4 iv = *(const float4*)(inv2 + yy * Ww + x);
            val = make_float4(v.x * iv.x, v.y * iv.y, v.z * iv.z, v.w * iv.w);
        }
        *(float4*)&s_f2[(c * SROWS + r) * SROW + 4 + x] = val;
    }
    // halo columns (x in -4..-1 and 64..67 are always out of bounds -> zero)
    for (int i = tid; i < Cc * SROWS * 2; i += NTHREADS) {
        int cr   = i >> 1;
        int side = i & 1;
        *(float4*)&s_f2[cr * SROW + side * 68] = make_float4(0.f, 0.f, 0.f, 0.f);
    }
    __syncthreads();

    // ---- compute
    const int warp = tid >> 5;        // dy index 0..8
    const int lane = tid & 31;
    const int ty   = lane >> 4;       // row within tile
    const int xg   = lane & 15;       // x-group (4 pixels)
    const int y    = y0 + ty;
    const int x0   = xg << 2;

    float acc[PATCH][4];
#pragma unroll
    for (int i = 0; i < PATCH; ++i) {
        acc[i][0] = 0.f; acc[i][1] = 0.f; acc[i][2] = 0.f; acc[i][3] = 0.f;
    }

    const float4* f1p = (const float4*)(f1 + b * CHW + y * Ww + x0); // +HW/4 per c
    const float*  s2p = &s_f2[(warp + ty) * SROW + x0];              // +SROWS*SROW per c

#pragma unroll 4
    for (int c = 0; c < Cc; ++c) {
        float4 a = __ldg(&f1p[c * (HW / 4)]);
        const float* s = s2p + c * (SROWS * SROW);
        float v[12];
        *(float4*)&v[0] = *(const float4*)(s);
        *(float4*)&v[4] = *(const float4*)(s + 4);
        *(float4*)&v[8] = *(const float4*)(s + 8);
#pragma unroll
        for (int dx = 0; dx < PATCH; ++dx) {
            acc[dx][0] += a.x * v[dx + 0];
            acc[dx][1] += a.y * v[dx + 1];
            acc[dx][2] += a.z * v[dx + 2];
            acc[dx][3] += a.w * v[dx + 3];
        }
    }

    // ---- epilogue: scale by f1's inverse norm, relu, store
    float4 iv1 = *(const float4*)(&g_inv[0][b][y * Ww + x0]);
    float* op = out + (size_t)(b * (PATCH * PATCH) + warp * PATCH) * HW + y * Ww + x0;
#pragma unroll
    for (int dx = 0; dx < PATCH; ++dx) {
        float4 o;
        o.x = fmaxf(acc[dx][0] * iv1.x, 0.f);
        o.y = fmaxf(acc[dx][1] * iv1.y, 0.f);
        o.z = fmaxf(acc[dx][2] * iv1.z, 0.f);
        o.w = fmaxf(acc[dx][3] * iv1.w, 0.f);
        *(float4*)(op + dx * HW) = o;
    }
}

// ---------------------------------------------------------------------------
extern "C" void kernel_launch(void* const* d_in, const int* in_sizes, int n_in,
                              void* d_out, int out_size) {
    const float* f1 = (const float*)d_in[0];
    const float* f2 = (const float*)d_in[1];
    float* out = (float*)d_out;

    cudaFuncSetAttribute(corr_kernel,
                         cudaFuncAttributeMaxDynamicSharedMemorySize, SMEM_BYTES);

    invnorm_kernel<<<128, 256>>>(f1, f2);
    corr_kernel<<<Bz * (Hh / TY), NTHREADS, SMEM_BYTES>>>(f1, f2, out);
}